// round 7
// baseline (speedup 1.0000x reference)
#include <cuda_runtime.h>
#include <cstdint>
#include <cstddef>

#define L2E 1.4426950408889634f
typedef unsigned long long u64;

__device__ __align__(16) float g_ptab[30000u * 1536u]; // pre-projected vocab
__device__ __align__(16) float g_hidden[128 * 512];    // [B, 2H] final hidden

__device__ __forceinline__ float ex2c(float y) {
    y = fminf(fmaxf(y, -126.f), 126.f);
    float r; asm("ex2.approx.f32 %0, %1;" : "=f"(r) : "f"(y)); return r;
}
__device__ __forceinline__ float rcp_(float x) {
    float r; asm("rcp.approx.f32 %0, %1;" : "=f"(r) : "f"(x)); return r;
}
__device__ __forceinline__ float sig_(float x) { return rcp_(1.f + ex2c(-x * L2E)); }
__device__ __forceinline__ float tanh_(float x) {
    float u = ex2c(2.f * L2E * x);
    return (u - 1.f) * rcp_(u + 1.f);
}
__device__ __forceinline__ u64 fma2(u64 a, u64 b, u64 c) {
    u64 d; asm("fma.rn.f32x2 %0, %1, %2, %3;" : "=l"(d) : "l"(a), "l"(b), "l"(c)); return d;
}
__device__ __forceinline__ float hsum(u64 v) {
    float x, y; asm("mov.b64 {%0,%1}, %2;" : "=f"(x), "=f"(y) : "l"(v)); return x + y;
}
__device__ __forceinline__ void cluster_sync_() {
    asm volatile("barrier.cluster.arrive.aligned;" ::: "memory");
    asm volatile("barrier.cluster.wait.aligned;" ::: "memory");
}
__device__ __forceinline__ void st_cluster_f32(uint32_t saddr, int rank, float v) {
    uint32_t ra;
    asm volatile("mapa.shared::cluster.u32 %0, %1, %2;" : "=r"(ra) : "r"(saddr), "r"(rank));
    asm volatile("st.shared::cluster.f32 [%0], %1;" :: "r"(ra), "f"(v));
}

// ---------------------------------------------------------------------------
// K1: ptab[30000,1536] = emb @ [Wf;Wb]^T + b.  Tiles 128(M) x 64(N), BK=32.
// 256 threads, thread tile 8x4, f32x2 k-packed accumulators.
// ---------------------------------------------------------------------------
__global__ void __launch_bounds__(256, 2)
k1_ptab(const float* __restrict__ emb,
        const float* __restrict__ Wf, const float* __restrict__ Wb,
        const float* __restrict__ bf, const float* __restrict__ bb)
{
    __shared__ __align__(16) float As[128 * 36];
    __shared__ __align__(16) float Ws[64 * 36];

    const int tid   = threadIdx.x;
    const int nBase = blockIdx.x * 64;
    const int mBase = blockIdx.y * 128;

    const float* Wsrc; const float* bsrc; int nOff;
    if (nBase < 768) { Wsrc = Wf; bsrc = bf; nOff = nBase; }
    else             { Wsrc = Wb; bsrc = bb; nOff = nBase - 768; }

    const int ty = tid >> 4;   // 0..15 -> 8 M-rows
    const int tx = tid & 15;   // 0..15 -> 4 N-cols

    u64 acc[8][4];
    #pragma unroll
    for (int j = 0; j < 8; ++j)
        #pragma unroll
        for (int n = 0; n < 4; ++n) acc[j][n] = 0ull;

    for (int kc = 0; kc < 256; kc += 32) {
        __syncthreads();
        #pragma unroll
        for (int q = 0; q < 4; ++q) {                 // A: 128x32
            int idx = tid * 4 + q;
            int r = idx >> 3, c4 = (idx & 7) << 2;
            int row = mBase + r; if (row > 29999) row = 29999;
            float4 v = *reinterpret_cast<const float4*>(emb + (size_t)row * 256 + kc + c4);
            *reinterpret_cast<float4*>(As + r * 36 + c4) = v;
        }
        #pragma unroll
        for (int q = 0; q < 2; ++q) {                 // W: 64x32
            int idx = tid * 2 + q;
            int r = idx >> 3, c4 = (idx & 7) << 2;
            float4 v = *reinterpret_cast<const float4*>(Wsrc + (size_t)(nOff + r) * 256 + kc + c4);
            *reinterpret_cast<float4*>(Ws + r * 36 + c4) = v;
        }
        __syncthreads();

        #pragma unroll
        for (int kk = 0; kk < 32; kk += 2) {
            u64 a2[8], w2[4];
            #pragma unroll
            for (int j = 0; j < 8; ++j)
                a2[j] = *reinterpret_cast<const u64*>(As + (ty * 8 + j) * 36 + kk);
            #pragma unroll
            for (int n = 0; n < 4; ++n)
                w2[n] = *reinterpret_cast<const u64*>(Ws + (tx * 4 + n) * 36 + kk);
            #pragma unroll
            for (int j = 0; j < 8; ++j)
                #pragma unroll
                for (int n = 0; n < 4; ++n)
                    acc[j][n] = fma2(a2[j], w2[n], acc[j][n]);
        }
    }

    float bias[4];
    #pragma unroll
    for (int n = 0; n < 4; ++n) bias[n] = bsrc[nOff + tx * 4 + n];

    #pragma unroll
    for (int j = 0; j < 8; ++j) {
        int row = mBase + ty * 8 + j;
        if (row < 30000) {
            float4 o;
            o.x = hsum(acc[j][0]) + bias[0];
            o.y = hsum(acc[j][1]) + bias[1];
            o.z = hsum(acc[j][2]) + bias[2];
            o.w = hsum(acc[j][3]) + bias[3];
            *reinterpret_cast<float4*>(g_ptab + (size_t)row * 1536 + nBase + tx * 4) = o;
        }
    }
}

// ---------------------------------------------------------------------------
// K2: recurrence. Grid 128, block 256, cluster 4.
// Cluster cid (0..31): dir = cid>>4, batches [8*(cid&15), +8).
// CTA rank owns global hidden dims [64*rank, +64) for all 3 gates.
// SMEM: Wsh[192][260] | hbuf[2][8][260]   (stride 260 floats = 1040 B, 16B-mult)
// Thread: warp w (local dims 8w..8w+7), lane m=l>>3 (dim pair 2m), n=l&7 (seq).
// ---------------------------------------------------------------------------
#define WSTR 260
#define HSTR 260
#define K2_SMEM ((192 * WSTR + 2 * 8 * HSTR) * 4)

__global__ void __cluster_dims__(4, 1, 1) __launch_bounds__(256, 1)
k2_gru(const int* __restrict__ tokens,
       const float* __restrict__ Whh_f, const float* __restrict__ bhh_f,
       const float* __restrict__ Whh_b, const float* __restrict__ bhh_b)
{
    extern __shared__ float smem[];
    float* Wsh  = smem;                    // 192 x WSTR
    float* hbuf = smem + 192 * WSTR;       // 2 x 8 x HSTR

    const int tid  = threadIdx.x;
    const int cid  = blockIdx.x >> 2;
    const int rank = blockIdx.x & 3;
    const int dir  = cid >> 4;
    const int qb   = cid & 15;

    const float* Whh = dir ? Whh_b : Whh_f;
    const float* bhh = dir ? bhh_b : bhh_f;

    const int w = tid >> 5;                 // warp 0..7
    const int l = tid & 31;
    const int m = l >> 3;                   // 0..3
    const int n = l & 7;                    // seq in cluster 0..7
    const int dloc = 8 * w + 2 * m;         // local dim (pair base) 0..62
    const int b = 8 * qb + n;               // batch row

    // Load W_hh slice: local row (g*64 + d) <- global row (g*256 + 64*rank + d)
    for (int idx = tid; idx < 192 * 64; idx += 256) {
        int row = idx >> 6;                 // 0..191
        int c4  = (idx & 63) << 2;
        int g = row >> 6, d = row & 63;
        float4 v = *reinterpret_cast<const float4*>(Whh + (size_t)(g * 256 + 64 * rank + d) * 256 + c4);
        *reinterpret_cast<float4*>(Wsh + row * WSTR + c4) = v;
    }
    // Zero h buffer 0
    for (int idx = tid; idx < 8 * HSTR; idx += 256) hbuf[idx] = 0.f;

    // Per-thread constants
    float bR[2], bZ[2], bN[2];
    #pragma unroll
    for (int j = 0; j < 2; ++j) {
        int gd = 64 * rank + dloc + j;
        bR[j] = bhh[0 * 256 + gd];
        bZ[j] = bhh[1 * 256 + gd];
        bN[j] = bhh[2 * 256 + gd];
    }
    const size_t pbase = (size_t)dir * 768 + 64 * rank + dloc;

    // xg prefetch for t=0
    float xc[3][2];
    {
        int tok = tokens[b * 512 + (dir ? 511 : 0)];
        const float* p = g_ptab + (size_t)tok * 1536 + pbase;
        #pragma unroll
        for (int g = 0; g < 3; ++g) { xc[g][0] = p[g * 256]; xc[g][1] = p[g * 256 + 1]; }
    }

    cluster_sync_();

    const float* w0  = Wsh + (0 * 64 + dloc) * WSTR;
    const float* w1  = Wsh + (1 * 64 + dloc) * WSTR;
    const float* w2p = Wsh + (2 * 64 + dloc) * WSTR;

    int cur = 0;
    for (int t = 0; t < 512; ++t) {
        // prefetch next step's xg (hidden under dot loop)
        float xn_[3][2];
        {
            int tn = (t < 511) ? t + 1 : 511;
            int tok = tokens[b * 512 + (dir ? 511 - tn : tn)];
            const float* p = g_ptab + (size_t)tok * 1536 + pbase;
            #pragma unroll
            for (int g = 0; g < 3; ++g) { xn_[g][0] = p[g * 256]; xn_[g][1] = p[g * 256 + 1]; }
        }

        const float* hc = hbuf + cur * 8 * HSTR + n * HSTR;
        u64 aR0 = 0, aR1 = 0, aZ0 = 0, aZ1 = 0, aN0 = 0, aN1 = 0;
        #pragma unroll 8
        for (int kk = 0; kk < 256; kk += 2) {
            u64 h2 = *reinterpret_cast<const u64*>(hc + kk);
            aR0 = fma2(*reinterpret_cast<const u64*>(w0 + kk),         h2, aR0);
            aR1 = fma2(*reinterpret_cast<const u64*>(w0 + WSTR + kk),  h2, aR1);
            aZ0 = fma2(*reinterpret_cast<const u64*>(w1 + kk),         h2, aZ0);
            aZ1 = fma2(*reinterpret_cast<const u64*>(w1 + WSTR + kk),  h2, aZ1);
            aN0 = fma2(*reinterpret_cast<const u64*>(w2p + kk),        h2, aN0);
            aN1 = fma2(*reinterpret_cast<const u64*>(w2p + WSTR + kk), h2, aN1);
        }

        float hrs[2] = { hsum(aR0) + bR[0], hsum(aR1) + bR[1] };
        float hzs[2] = { hsum(aZ0) + bZ[0], hsum(aZ1) + bZ[1] };
        float hns[2] = { hsum(aN0) + bN[0], hsum(aN1) + bN[1] };

        float* hnxt = hbuf + (cur ^ 1) * 8 * HSTR + n * HSTR;
        #pragma unroll
        for (int j = 0; j < 2; ++j) {
            int gd = 64 * rank + dloc + j;
            float r  = sig_(xc[0][j] + hrs[j]);
            float z  = sig_(xc[1][j] + hzs[j]);
            float nn = tanh_(xc[2][j] + r * hns[j]);
            float hp = hc[gd];
            float hnew = (1.f - z) * nn + z * hp;
            uint32_t saddr = (uint32_t)__cvta_generic_to_shared(hnxt + gd);
            #pragma unroll
            for (int rk = 0; rk < 4; ++rk) st_cluster_f32(saddr, rk, hnew);
        }

        cluster_sync_();
        #pragma unroll
        for (int g = 0; g < 3; ++g) { xc[g][0] = xn_[g][0]; xc[g][1] = xn_[g][1]; }
        cur ^= 1;
    }

    // final h lives in hbuf[cur]
    const float* hf = hbuf + cur * 8 * HSTR + n * HSTR;
    #pragma unroll
    for (int j = 0; j < 2; ++j) {
        int gd = 64 * rank + dloc + j;
        g_hidden[(size_t)b * 512 + dir * 256 + gd] = hf[gd];
    }
}

// ---------------------------------------------------------------------------
// K3: logits[128,10] = hidden @ W_lin^T + b_lin. Block = batch, warp = class.
// ---------------------------------------------------------------------------
__global__ void __launch_bounds__(320)
k3_head(const float* __restrict__ Wl, const float* __restrict__ bl,
        float* __restrict__ out)
{
    int b = blockIdx.x;
    int c = threadIdx.x >> 5;     // 0..9
    int lane = threadIdx.x & 31;

    const float* h = g_hidden + (size_t)b * 512;
    const float* wr = Wl + (size_t)c * 512;
    float acc = 0.f;
    #pragma unroll
    for (int k = lane; k < 512; k += 32) acc += h[k] * wr[k];
    #pragma unroll
    for (int s = 16; s > 0; s >>= 1) acc += __shfl_xor_sync(0xffffffffu, acc, s);
    if (lane == 0) out[b * 10 + c] = acc + bl[c];
}

// ---------------------------------------------------------------------------
extern "C" void kernel_launch(void* const* d_in, const int* in_sizes, int n_in,
                              void* d_out, int out_size)
{
    (void)in_sizes; (void)n_in; (void)out_size;
    const int*   tokens = (const int*)  d_in[0];
    const float* emb    = (const float*)d_in[1];
    const float* Wih_f  = (const float*)d_in[2];
    const float* Whh_f  = (const float*)d_in[3];
    const float* bih_f  = (const float*)d_in[4];
    const float* bhh_f  = (const float*)d_in[5];
    const float* Wih_b  = (const float*)d_in[6];
    const float* Whh_b  = (const float*)d_in[7];
    const float* bih_b  = (const float*)d_in[8];
    const float* bhh_b  = (const float*)d_in[9];
    const float* Wlin   = (const float*)d_in[10];
    const float* blin   = (const float*)d_in[11];
    float* out = (float*)d_out;

    cudaFuncSetAttribute(k2_gru, cudaFuncAttributeMaxDynamicSharedMemorySize, K2_SMEM);

    dim3 g1(1536 / 64, (30000 + 127) / 128);
    k1_ptab<<<g1, 256>>>(emb, Wih_f, Wih_b, bih_f, bih_b);

    k2_gru<<<128, 256, K2_SMEM>>>(tokens, Whh_f, bhh_f, Whh_b, bhh_b);

    k3_head<<<128, 320>>>(Wlin, blin, out);
}

// round 8
// speedup vs baseline: 1.1867x; 1.1867x over previous
#include <cuda_runtime.h>
#include <cstdint>
#include <cstddef>

#define L2E 1.4426950408889634f
typedef unsigned long long u64;

__device__ __align__(16) float g_ptab[30000u * 1536u]; // pre-projected vocab
__device__ __align__(16) float g_hidden[128 * 512];    // [B, 2H] final hidden

__device__ __forceinline__ float ex2c(float y) {
    y = fminf(fmaxf(y, -126.f), 126.f);
    float r; asm("ex2.approx.f32 %0, %1;" : "=f"(r) : "f"(y)); return r;
}
__device__ __forceinline__ float rcp_(float x) {
    float r; asm("rcp.approx.f32 %0, %1;" : "=f"(r) : "f"(x)); return r;
}
__device__ __forceinline__ float sig_(float x) { return rcp_(1.f + ex2c(-x * L2E)); }
__device__ __forceinline__ float tanh_(float x) {
    float u = ex2c(2.f * L2E * x);
    return (u - 1.f) * rcp_(u + 1.f);
}
__device__ __forceinline__ u64 fma2(u64 a, u64 b, u64 c) {
    u64 d; asm("fma.rn.f32x2 %0, %1, %2, %3;" : "=l"(d) : "l"(a), "l"(b), "l"(c)); return d;
}
__device__ __forceinline__ float hsum(u64 v) {
    float x, y; asm("mov.b64 {%0,%1}, %2;" : "=f"(x), "=f"(y) : "l"(v)); return x + y;
}
__device__ __forceinline__ u64 pack2(float lo, float hi) {
    u64 v; asm("mov.b64 %0, {%1,%2};" : "=l"(v) : "f"(lo), "f"(hi)); return v;
}
__device__ __forceinline__ void cluster_sync_() {
    asm volatile("barrier.cluster.arrive.aligned;" ::: "memory");
    asm volatile("barrier.cluster.wait.aligned;" ::: "memory");
}
__device__ __forceinline__ uint32_t mapa_(uint32_t saddr, int rank) {
    uint32_t ra;
    asm volatile("mapa.shared::cluster.u32 %0, %1, %2;" : "=r"(ra) : "r"(saddr), "r"(rank));
    return ra;
}
__device__ __forceinline__ void st_cluster_u64(uint32_t ra, u64 v) {
    asm volatile("st.shared::cluster.u64 [%0], %1;" :: "r"(ra), "l"(v));
}

// ---------------------------------------------------------------------------
// K1: ptab[30000,1536] = emb @ [Wf;Wb]^T + b. Tiles 128(M) x 64(N), BK=32.
// 256 threads, thread tile 8 M x 4 N, f32x2 k-packed accumulators.
// Stride 34 + column remap (tx + 16n) => bank-conflict-free LDS.
// ---------------------------------------------------------------------------
#define AST 34
#define WST 34

__global__ void __launch_bounds__(256, 2)
k1_ptab(const float* __restrict__ emb,
        const float* __restrict__ Wf, const float* __restrict__ Wb,
        const float* __restrict__ bf, const float* __restrict__ bb)
{
    __shared__ __align__(16) float As[128 * AST];
    __shared__ __align__(16) float Ws[64 * WST];

    const int tid   = threadIdx.x;
    const int nBase = blockIdx.x * 64;
    const int mBase = blockIdx.y * 128;

    const float* Wsrc; const float* bsrc; int nOff;
    if (nBase < 768) { Wsrc = Wf; bsrc = bf; nOff = nBase; }
    else             { Wsrc = Wb; bsrc = bb; nOff = nBase - 768; }

    const int ty = tid >> 4;   // 0..15 -> 8 M-rows (ty*8+j)
    const int tx = tid & 15;   // 0..15 -> 4 N-cols (tx+16n)

    u64 acc[8][4];
    #pragma unroll
    for (int j = 0; j < 8; ++j)
        #pragma unroll
        for (int n = 0; n < 4; ++n) acc[j][n] = 0ull;

    for (int kc = 0; kc < 256; kc += 32) {
        __syncthreads();
        // A tile 128x32: 1024 float4 global loads, stored as 2x float2
        #pragma unroll
        for (int q = 0; q < 4; ++q) {
            int idx = q * 256 + tid;          // 0..1023
            int r = idx >> 3, c4 = (idx & 7) << 2;
            int row = mBase + r; if (row > 29999) row = 29999;
            float4 v = *reinterpret_cast<const float4*>(emb + (size_t)row * 256 + kc + c4);
            float* d = As + r * AST + c4;
            *reinterpret_cast<float2*>(d)     = make_float2(v.x, v.y);
            *reinterpret_cast<float2*>(d + 2) = make_float2(v.z, v.w);
        }
        // W tile 64x32: 512 float4 global loads
        #pragma unroll
        for (int q = 0; q < 2; ++q) {
            int idx = q * 256 + tid;          // 0..511
            int r = idx >> 3, c4 = (idx & 7) << 2;
            float4 v = *reinterpret_cast<const float4*>(Wsrc + (size_t)(nOff + r) * 256 + kc + c4);
            float* d = Ws + r * WST + c4;
            *reinterpret_cast<float2*>(d)     = make_float2(v.x, v.y);
            *reinterpret_cast<float2*>(d + 2) = make_float2(v.z, v.w);
        }
        __syncthreads();

        #pragma unroll
        for (int kk = 0; kk < 32; kk += 2) {
            u64 a2[8], w2[4];
            #pragma unroll
            for (int j = 0; j < 8; ++j)
                a2[j] = *reinterpret_cast<const u64*>(As + (ty * 8 + j) * AST + kk);
            #pragma unroll
            for (int n = 0; n < 4; ++n)
                w2[n] = *reinterpret_cast<const u64*>(Ws + (tx + 16 * n) * WST + kk);
            #pragma unroll
            for (int j = 0; j < 8; ++j)
                #pragma unroll
                for (int n = 0; n < 4; ++n)
                    acc[j][n] = fma2(a2[j], w2[n], acc[j][n]);
        }
    }

    float bias[4];
    #pragma unroll
    for (int n = 0; n < 4; ++n) bias[n] = bsrc[nOff + tx + 16 * n];

    #pragma unroll
    for (int j = 0; j < 8; ++j) {
        int row = mBase + ty * 8 + j;
        if (row < 30000) {
            float* o = g_ptab + (size_t)row * 1536 + nBase + tx;
            #pragma unroll
            for (int n = 0; n < 4; ++n)
                o[16 * n] = hsum(acc[j][n]) + bias[n];
        }
    }
}

// ---------------------------------------------------------------------------
// K2: recurrence. Grid 128, block 256, cluster 4.
// Cluster cid (0..31): dir = cid>>4, batches [8*(cid&15), +8).
// CTA rank owns global hidden dims [64*rank, +64) for all 3 gates.
// SMEM: Wsh[192][260] | hbuf[2][8][260]
// Thread: warp w (local dims 8w..8w+7), lane m=l>>3 (dim pair 2m), n=l&7 (seq).
// Dot loop: LDS.128 (4 k-values), f32x2 FMAs. DSMEM addrs hoisted; u64 stores.
// ---------------------------------------------------------------------------
#define WSTR 260
#define HSTR 260
#define K2_SMEM ((192 * WSTR + 2 * 8 * HSTR) * 4)

__global__ void __cluster_dims__(4, 1, 1) __launch_bounds__(256, 1)
k2_gru(const int* __restrict__ tokens,
       const float* __restrict__ Whh_f, const float* __restrict__ bhh_f,
       const float* __restrict__ Whh_b, const float* __restrict__ bhh_b)
{
    extern __shared__ float smem[];
    float* Wsh  = smem;                    // 192 x WSTR
    float* hbuf = smem + 192 * WSTR;       // 2 x 8 x HSTR

    const int tid  = threadIdx.x;
    const int cid  = blockIdx.x >> 2;
    const int rank = blockIdx.x & 3;
    const int dir  = cid >> 4;
    const int qb   = cid & 15;

    const float* Whh = dir ? Whh_b : Whh_f;
    const float* bhh = dir ? bhh_b : bhh_f;

    const int w = tid >> 5;                 // warp 0..7
    const int l = tid & 31;
    const int m = l >> 3;                   // 0..3
    const int n = l & 7;                    // seq in cluster 0..7
    const int dloc = 8 * w + 2 * m;         // local dim pair base 0..62
    const int b = 8 * qb + n;               // batch row
    const int gd0 = 64 * rank + dloc;       // global dim pair base

    // Load W_hh slice: local row (g*64 + d) <- global row (g*256 + 64*rank + d)
    for (int idx = tid; idx < 192 * 64; idx += 256) {
        int row = idx >> 6;
        int c4  = (idx & 63) << 2;
        int g = row >> 6, d = row & 63;
        float4 v = *reinterpret_cast<const float4*>(Whh + (size_t)(g * 256 + 64 * rank + d) * 256 + c4);
        *reinterpret_cast<float4*>(Wsh + row * WSTR + c4) = v;
    }
    for (int idx = tid; idx < 8 * HSTR; idx += 256) hbuf[idx] = 0.f;

    float bR[2], bZ[2], bN[2];
    #pragma unroll
    for (int j = 0; j < 2; ++j) {
        bR[j] = bhh[0 * 256 + gd0 + j];
        bZ[j] = bhh[1 * 256 + gd0 + j];
        bN[j] = bhh[2 * 256 + gd0 + j];
    }
    const size_t pbase = (size_t)dir * 768 + gd0;

    // Hoisted DSMEM target addresses (2 buffers x 4 ranks)
    uint32_t pa0[4], pa1[4];
    {
        uint32_t s0 = (uint32_t)__cvta_generic_to_shared(hbuf + 0 * 8 * HSTR + n * HSTR + gd0);
        uint32_t s1 = (uint32_t)__cvta_generic_to_shared(hbuf + 1 * 8 * HSTR + n * HSTR + gd0);
        #pragma unroll
        for (int rk = 0; rk < 4; ++rk) { pa0[rk] = mapa_(s0, rk); pa1[rk] = mapa_(s1, rk); }
    }

    // xg prefetch for t=0
    float xc[3][2];
    {
        int tok = tokens[b * 512 + (dir ? 511 : 0)];
        const float* p = g_ptab + (size_t)tok * 1536 + pbase;
        #pragma unroll
        for (int g = 0; g < 3; ++g) { xc[g][0] = p[g * 256]; xc[g][1] = p[g * 256 + 1]; }
    }

    cluster_sync_();

    const float* w0  = Wsh + (0 * 64 + dloc) * WSTR;
    const float* w1  = Wsh + (1 * 64 + dloc) * WSTR;
    const float* w2p = Wsh + (2 * 64 + dloc) * WSTR;

    int cur = 0;
    for (int t = 0; t < 512; ++t) {
        // prefetch next step's xg (hidden under dot loop)
        float xn_[3][2];
        {
            int tn = (t < 511) ? t + 1 : 511;
            int tok = tokens[b * 512 + (dir ? 511 - tn : tn)];
            const float* p = g_ptab + (size_t)tok * 1536 + pbase;
            #pragma unroll
            for (int g = 0; g < 3; ++g) { xn_[g][0] = p[g * 256]; xn_[g][1] = p[g * 256 + 1]; }
        }

        const float* hc = hbuf + cur * 8 * HSTR + n * HSTR;
        u64 aR0 = 0, aR1 = 0, aZ0 = 0, aZ1 = 0, aN0 = 0, aN1 = 0;
        #pragma unroll 8
        for (int kk = 0; kk < 256; kk += 4) {
            ulonglong2 h4 = *reinterpret_cast<const ulonglong2*>(hc + kk);
            ulonglong2 wa = *reinterpret_cast<const ulonglong2*>(w0 + kk);
            ulonglong2 wb = *reinterpret_cast<const ulonglong2*>(w0 + WSTR + kk);
            aR0 = fma2(wa.x, h4.x, aR0); aR0 = fma2(wa.y, h4.y, aR0);
            aR1 = fma2(wb.x, h4.x, aR1); aR1 = fma2(wb.y, h4.y, aR1);
            wa = *reinterpret_cast<const ulonglong2*>(w1 + kk);
            wb = *reinterpret_cast<const ulonglong2*>(w1 + WSTR + kk);
            aZ0 = fma2(wa.x, h4.x, aZ0); aZ0 = fma2(wa.y, h4.y, aZ0);
            aZ1 = fma2(wb.x, h4.x, aZ1); aZ1 = fma2(wb.y, h4.y, aZ1);
            wa = *reinterpret_cast<const ulonglong2*>(w2p + kk);
            wb = *reinterpret_cast<const ulonglong2*>(w2p + WSTR + kk);
            aN0 = fma2(wa.x, h4.x, aN0); aN0 = fma2(wa.y, h4.y, aN0);
            aN1 = fma2(wb.x, h4.x, aN1); aN1 = fma2(wb.y, h4.y, aN1);
        }

        float hrs[2] = { hsum(aR0) + bR[0], hsum(aR1) + bR[1] };
        float hzs[2] = { hsum(aZ0) + bZ[0], hsum(aZ1) + bZ[1] };
        float hns[2] = { hsum(aN0) + bN[0], hsum(aN1) + bN[1] };

        u64 hp2 = *reinterpret_cast<const u64*>(hc + gd0);
        float hp[2]; asm("mov.b64 {%0,%1}, %2;" : "=f"(hp[0]), "=f"(hp[1]) : "l"(hp2));

        float hnew[2];
        #pragma unroll
        for (int j = 0; j < 2; ++j) {
            float r  = sig_(xc[0][j] + hrs[j]);
            float z  = sig_(xc[1][j] + hzs[j]);
            float nn = tanh_(xc[2][j] + r * hns[j]);
            hnew[j] = (1.f - z) * nn + z * hp[j];
        }
        u64 hv = pack2(hnew[0], hnew[1]);
        #pragma unroll
        for (int rk = 0; rk < 4; ++rk)
            st_cluster_u64(cur ? pa0[rk] : pa1[rk], hv);

        cluster_sync_();
        #pragma unroll
        for (int g = 0; g < 3; ++g) { xc[g][0] = xn_[g][0]; xc[g][1] = xn_[g][1]; }
        cur ^= 1;
    }

    const float* hf = hbuf + cur * 8 * HSTR + n * HSTR;
    #pragma unroll
    for (int j = 0; j < 2; ++j)
        g_hidden[(size_t)b * 512 + dir * 256 + gd0 + j] = hf[gd0 + j];
}

// ---------------------------------------------------------------------------
// K3: logits[128,10] = hidden @ W_lin^T + b_lin. Block = batch, warp = class.
// ---------------------------------------------------------------------------
__global__ void __launch_bounds__(320)
k3_head(const float* __restrict__ Wl, const float* __restrict__ bl,
        float* __restrict__ out)
{
    int b = blockIdx.x;
    int c = threadIdx.x >> 5;
    int lane = threadIdx.x & 31;

    const float* h = g_hidden + (size_t)b * 512;
    const float* wr = Wl + (size_t)c * 512;
    float acc = 0.f;
    #pragma unroll
    for (int k = lane; k < 512; k += 32) acc += h[k] * wr[k];
    #pragma unroll
    for (int s = 16; s > 0; s >>= 1) acc += __shfl_xor_sync(0xffffffffu, acc, s);
    if (lane == 0) out[b * 10 + c] = acc + bl[c];
}

// ---------------------------------------------------------------------------
extern "C" void kernel_launch(void* const* d_in, const int* in_sizes, int n_in,
                              void* d_out, int out_size)
{
    (void)in_sizes; (void)n_in; (void)out_size;
    const int*   tokens = (const int*)  d_in[0];
    const float* emb    = (const float*)d_in[1];
    const float* Wih_f  = (const float*)d_in[2];
    const float* Whh_f  = (const float*)d_in[3];
    const float* bih_f  = (const float*)d_in[4];
    const float* bhh_f  = (const float*)d_in[5];
    const float* Wih_b  = (const float*)d_in[6];
    const float* Whh_b  = (const float*)d_in[7];
    const float* bih_b  = (const float*)d_in[8];
    const float* bhh_b  = (const float*)d_in[9];
    const float* Wlin   = (const float*)d_in[10];
    const float* blin   = (const float*)d_in[11];
    float* out = (float*)d_out;

    cudaFuncSetAttribute(k2_gru, cudaFuncAttributeMaxDynamicSharedMemorySize, K2_SMEM);

    dim3 g1(1536 / 64, (30000 + 127) / 128);
    k1_ptab<<<g1, 256>>>(emb, Wih_f, Wih_b, bih_f, bih_b);

    k2_gru<<<128, 256, K2_SMEM>>>(tokens, Whh_f, bhh_f, Whh_b, bhh_b);

    k3_head<<<128, 320>>>(Wlin, blin, out);
}